// round 14
// baseline (speedup 1.0000x reference)
#include <cuda_runtime.h>
#include <cuda_fp16.h>
#include <cstdint>
#include <cstddef>

#define TTOK 2048
#define DDIM 2048
#define FDIM 4096
#define NEXP 8
#define NPOS (TTOK * 2)
#define WSZ ((size_t)NEXP * DDIM * FDIM)

#define ASTR 80                        // A smem row stride bytes (32 fp16 + 16B pad)
#define BSTR 272                       // B smem row stride bytes (128 fp16 + 16B pad)
#define A_SZ (128 * ASTR)              // 10240
#define B_SZ (32 * BSTR)               // 8704
#define STAGE (A_SZ + B_SZ)            // 18944
#define NSTG 3
#define DYNSM (NSTG * STAGE)           // 56832

// ---------------- scratch ----------------
__device__ int    g_offsets[NEXP + 1];
__device__ int    g_topk_idx[NPOS];
__device__ float  g_topk_w[NPOS];
__device__ int    g_row_token[NPOS];
__device__ float  g_row_w[NPOS];
__device__ int    g_token_pos[NPOS];
__device__ __half g_act[(size_t)NPOS * FDIM];
__device__ float  g_y[(size_t)NPOS * DDIM];
__device__ __half g_x16[(size_t)TTOK * DDIM];
__device__ __half g_wg16[WSZ];
__device__ __half g_wu16[WSZ];
__device__ __half g_wd16[WSZ];

// ---------------- helpers ----------------
__device__ __forceinline__ uint32_t smem_u32(const void* p) {
    uint32_t a;
    asm("{ .reg .u64 t; cvta.to.shared.u64 t, %1; cvt.u32.u64 %0, t; }" : "=r"(a) : "l"(p));
    return a;
}
__device__ __forceinline__ uint32_t pack2(float lo, float hi) {
    uint32_t r;
    asm("cvt.rn.f16x2.f32 %0, %1, %2;" : "=r"(r) : "f"(hi), "f"(lo));
    return r;
}
__device__ __forceinline__ void ldsm4(uint32_t* r, uint32_t a) {
    asm volatile("ldmatrix.sync.aligned.m8n8.x4.shared.b16 {%0,%1,%2,%3}, [%4];"
                 : "=r"(r[0]), "=r"(r[1]), "=r"(r[2]), "=r"(r[3]) : "r"(a));
}
__device__ __forceinline__ void ldsm4t(uint32_t* r, uint32_t a) {
    asm volatile("ldmatrix.sync.aligned.m8n8.x4.trans.shared.b16 {%0,%1,%2,%3}, [%4];"
                 : "=r"(r[0]), "=r"(r[1]), "=r"(r[2]), "=r"(r[3]) : "r"(a));
}
__device__ __forceinline__ void mma16(float* c, const uint32_t* a, const uint32_t* b) {
    asm volatile(
        "mma.sync.aligned.m16n8k16.row.col.f32.f16.f16.f32 "
        "{%0,%1,%2,%3},{%4,%5,%6,%7},{%8,%9},{%0,%1,%2,%3};"
        : "+f"(c[0]), "+f"(c[1]), "+f"(c[2]), "+f"(c[3])
        : "r"(a[0]), "r"(a[1]), "r"(a[2]), "r"(a[3]), "r"(b[0]), "r"(b[1]));
}
#define CPA16(dst, src) \
    asm volatile("cp.async.cg.shared.global [%0], [%1], 16;" :: "r"(dst), "l"(src))
#define CPCOMMIT() asm volatile("cp.async.commit_group;" ::: "memory")
#define CPWAIT1()  asm volatile("cp.async.wait_group 1;" ::: "memory")

__device__ __forceinline__ float gelu_tanh(float x) {
    float x3 = x * x * x;
    return 0.5f * x * (1.0f + tanhf(0.7978845608028654f * (x + 0.044715f * x3)));
}

// ---------------- weight convert: fp32 -> fp16, streaming, 3 arrays in one launch ------
// grid (4096, 3) x 256. Per array: 16,777,216 float4 = 4096*1024*4 exactly (4 outer iters).
__global__ void k_cvtw(const float4* __restrict__ s0, const float4* __restrict__ s1,
                       const float4* __restrict__ s2,
                       uint2* __restrict__ d0, uint2* __restrict__ d1, uint2* __restrict__ d2) {
    const float4* s = (blockIdx.y == 0) ? s0 : ((blockIdx.y == 1) ? s1 : s2);
    uint2* d = (blockIdx.y == 0) ? d0 : ((blockIdx.y == 1) ? d1 : d2);
    int i = blockIdx.x * 1024 + threadIdx.x;
    const int stride = 4096 * 1024;
#pragma unroll 1
    for (int it = 0; it < 4; it++, i += stride) {
        float4 v0 = __ldcs(&s[i]);
        float4 v1 = __ldcs(&s[i + 256]);
        float4 v2 = __ldcs(&s[i + 512]);
        float4 v3 = __ldcs(&s[i + 768]);
        uint2 o0, o1, o2, o3;
        o0.x = pack2(v0.x, v0.y); o0.y = pack2(v0.z, v0.w);
        o1.x = pack2(v1.x, v1.y); o1.y = pack2(v1.z, v1.w);
        o2.x = pack2(v2.x, v2.y); o2.y = pack2(v2.z, v2.w);
        o3.x = pack2(v3.x, v3.y); o3.y = pack2(v3.z, v3.w);
        d[i] = o0;
        d[i + 256] = o1;
        d[i + 512] = o2;
        d[i + 768] = o3;
    }
}

// ---------------- router (+ fused hs fp32->fp16 convert) ----------------
__global__ void k_router(const float* __restrict__ hs, const float* __restrict__ gw) {
    const int warp = threadIdx.x >> 5;
    const int lane = threadIdx.x & 31;
    const int t = blockIdx.x * 8 + warp;
    if (t >= TTOK) return;
    float acc[NEXP];
#pragma unroll
    for (int e = 0; e < NEXP; e++) acc[e] = 0.0f;
    const float2* hrow2 = (const float2*)(hs + (size_t)t * DDIM);
    uint32_t* xrow = (uint32_t*)(g_x16 + (size_t)t * DDIM);
    for (int i = lane; i < DDIM / 2; i += 32) {
        float2 x = hrow2[i];
        xrow[i] = pack2(x.x, x.y);
        const float* g0 = gw + (size_t)(2 * i) * NEXP;
#pragma unroll
        for (int e = 0; e < NEXP; e++)
            acc[e] = fmaf(x.x, g0[e], fmaf(x.y, g0[NEXP + e], acc[e]));
    }
#pragma unroll
    for (int e = 0; e < NEXP; e++) {
#pragma unroll
        for (int o = 16; o > 0; o >>= 1) acc[e] += __shfl_xor_sync(0xffffffffu, acc[e], o);
    }
    if (lane == 0) {
        float l[NEXP];
#pragma unroll
        for (int e = 0; e < NEXP; e++) l[e] = tanhf(acc[e] / 30.0f) * 30.0f;
        int i0 = 0;
#pragma unroll
        for (int e = 1; e < NEXP; e++) if (l[e] > l[i0]) i0 = e;
        int i1 = -1;
#pragma unroll
        for (int e = 0; e < NEXP; e++) {
            if (e == i0) continue;
            if (i1 < 0 || l[e] > l[i1]) i1 = e;
        }
        float ee = expf(l[i1] - l[i0]);
        g_topk_idx[t * 2 + 0] = i0;
        g_topk_idx[t * 2 + 1] = i1;
        g_topk_w[t * 2 + 0] = 1.0f / (1.0f + ee);
        g_topk_w[t * 2 + 1] = ee / (1.0f + ee);
    }
}

// ---------------- prep: counts + offsets + fill (one block) ----------------
__global__ void k_prep() {
    __shared__ int cnt[NEXP];
    __shared__ int fill[NEXP];
    const int tid = threadIdx.x;
    if (tid < NEXP) cnt[tid] = 0;
    __syncthreads();
    for (int i = tid; i < NPOS; i += blockDim.x) atomicAdd(&cnt[g_topk_idx[i]], 1);
    __syncthreads();
    if (tid == 0) {
        int o = 0;
#pragma unroll
        for (int e = 0; e < NEXP; e++) { g_offsets[e] = o; fill[e] = o; o += cnt[e]; }
        g_offsets[NEXP] = o;
    }
    __syncthreads();
    for (int i = tid; i < NPOS; i += blockDim.x) {
        const int e = g_topk_idx[i];
        const int pos = atomicAdd(&fill[e], 1);
        g_row_token[pos] = i >> 1;
        g_row_w[pos] = g_topk_w[i];
        g_token_pos[i] = pos;
    }
}

// ============ mlp1: act = gelu(X@Wg) * (X@Wu) ============
// 256 threads = 8 warps (2m x 4n), CTA tile 128x128 (64 gate + 64 up interleaved by 8 cols),
// K-chunk 32; A and B both via cp.async from fp16 (2+2 ops/thread/chunk). 3-stage ring.
__global__ void __launch_bounds__(256, 2) k_mlp1() {
    extern __shared__ uint8_t dsm[];
    const int e = blockIdx.z;
    const int seg_beg = g_offsets[e];
    const int seg_end = g_offsets[e + 1];
    if ((int)blockIdx.x * 128 >= seg_end - seg_beg) return;
    const int pos_base = seg_beg + blockIdx.x * 128;
    const int f0 = blockIdx.y * 64;

    const uint32_t sbase = smem_u32(dsm);
    const int tid = threadIdx.x;
    const int lane = tid & 31;
    const int w = tid >> 5, wm = w & 1, wn = w >> 1;
    const int grp = lane >> 3;

    // A producer: row tid>>1 (0..127), half tid&1; per-row gathered token pointer
    int apos = pos_base + (tid >> 1);
    if (apos >= seg_end) apos = seg_end - 1;
    const __half* asrc = g_x16 + (size_t)g_row_token[apos] * DDIM + (tid & 1) * 16;
    const uint32_t adst = (uint32_t)(tid >> 1) * ASTR + (uint32_t)(tid & 1) * 32;

    // B producer: h = gate/up, krow = u>>2 (0..31), c = u&3.
    // Thread covers f-cols [8c,8c+8) and [8c+32,8c+40); smem stores 128B apart.
    const int h = tid >> 7;
    const int u = tid & 127;
    const int krow = u >> 2;
    const int c = u & 3;
    const __half* bsrc = (h ? g_wu16 : g_wg16) + (size_t)e * DDIM * FDIM +
                         (size_t)krow * FDIM + f0 + c * 8;
    const uint32_t bdst0 = A_SZ + (uint32_t)krow * BSTR + (uint32_t)c * 32 + (uint32_t)h * 16;

    float acc[4][4][4];
#pragma unroll
    for (int a = 0; a < 4; a++)
#pragma unroll
        for (int b = 0; b < 4; b++)
#pragma unroll
            for (int i = 0; i < 4; i++) acc[a][b][i] = 0.0f;

    const int KT = DDIM / 32;  // 64

    // prologue: fill stages 0,1
#pragma unroll 1
    for (int s = 0; s < 2; s++) {
        const uint32_t st = sbase + s * STAGE;
        const size_t k0 = (size_t)s * 32;
        CPA16(st + adst, asrc + k0);
        CPA16(st + adst + 16, asrc + k0 + 8);
        CPA16(st + bdst0, bsrc + k0 * FDIM);
        CPA16(st + bdst0 + 128, bsrc + k0 * FDIM + 32);
        CPCOMMIT();
    }

#pragma unroll 1
    for (int c2 = 0; c2 < KT; c2++) {
        CPWAIT1();
        __syncthreads();
        if (c2 + 2 < KT) {
            const uint32_t st = sbase + ((c2 + 2) % NSTG) * STAGE;
            const size_t k0 = (size_t)(c2 + 2) * 32;
            CPA16(st + adst, asrc + k0);
            CPA16(st + adst + 16, asrc + k0 + 8);
            CPA16(st + bdst0, bsrc + k0 * FDIM);
            CPA16(st + bdst0 + 128, bsrc + k0 * FDIM + 32);
        }
        CPCOMMIT();
        // compute chunk c2
        const uint32_t sA = sbase + (c2 % NSTG) * STAGE;
        const uint32_t sB = sA + A_SZ;
#pragma unroll
        for (int ks = 0; ks < 2; ks++) {
            uint32_t bfr[4][2];
#pragma unroll
            for (int hn = 0; hn < 2; hn++) {
                uint32_t r[4];
                ldsm4t(r, sB + (uint32_t)(ks * 16 + (grp & 1) * 8 + (lane & 7)) * BSTR +
                           (uint32_t)(wn * 32 + hn * 16 + (grp >> 1) * 8) * 2);
                bfr[hn * 2 + 0][0] = r[0]; bfr[hn * 2 + 0][1] = r[1];
                bfr[hn * 2 + 1][0] = r[2]; bfr[hn * 2 + 1][1] = r[3];
            }
#pragma unroll
            for (int mt = 0; mt < 4; mt++) {
                uint32_t afr[4];
                ldsm4(afr, sA + (uint32_t)(wm * 64 + mt * 16 + (grp & 1) * 8 + (lane & 7)) * ASTR +
                           (uint32_t)(ks * 16 + (grp >> 1) * 8) * 2);
#pragma unroll
                for (int nt = 0; nt < 4; nt++) mma16(acc[mt][nt], afr, bfr[nt]);
            }
        }
    }

    // epilogue: nt even = gate, nt odd = up (same 8 f-cols)
#pragma unroll
    for (int mt = 0; mt < 4; mt++) {
        const int r0 = pos_base + wm * 64 + mt * 16 + (lane >> 2);
#pragma unroll
        for (int hn = 0; hn < 2; hn++) {
            const int fc = f0 + (wn * 2 + hn) * 8 + 2 * (lane & 3);
            const float* g = acc[mt][2 * hn];
            const float* uq = acc[mt][2 * hn + 1];
            if (r0 < seg_end)
                *(uint32_t*)(&g_act[(size_t)r0 * FDIM + fc]) =
                    pack2(gelu_tanh(g[0]) * uq[0], gelu_tanh(g[1]) * uq[1]);
            if (r0 + 8 < seg_end)
                *(uint32_t*)(&g_act[(size_t)(r0 + 8) * FDIM + fc]) =
                    pack2(gelu_tanh(g[2]) * uq[2], gelu_tanh(g[3]) * uq[3]);
        }
    }
}

// ============ mlp2: y = w * (act @ Wd) ============
__global__ void __launch_bounds__(256, 2) k_mlp2() {
    extern __shared__ uint8_t dsm[];
    const int e = blockIdx.z;
    const int seg_beg = g_offsets[e];
    const int seg_end = g_offsets[e + 1];
    if ((int)blockIdx.x * 128 >= seg_end - seg_beg) return;
    const int pos_base = seg_beg + blockIdx.x * 128;
    const int n0 = blockIdx.y * 128;

    const uint32_t sbase = smem_u32(dsm);
    const int tid = threadIdx.x;
    const int lane = tid & 31;
    const int w = tid >> 5, wm = w & 1, wn = w >> 1;
    const int grp = lane >> 3;

    int apos = pos_base + (tid >> 1);
    if (apos >= seg_end) apos = seg_end - 1;
    const __half* asrc = g_act + (size_t)apos * FDIM + (tid & 1) * 16;
    const uint32_t adst = (uint32_t)(tid >> 1) * ASTR + (uint32_t)(tid & 1) * 32;

    // B producer: krow = tid>>3 (0..31), c8 = tid&7; covers n-cols [8c8,+8) and [8c8+64,+8).
    const int krow = tid >> 3;
    const int c8 = tid & 7;
    const __half* bsrc = g_wd16 + (size_t)e * FDIM * DDIM + (size_t)krow * DDIM + n0 + c8 * 8;
    const uint32_t bdst0 = A_SZ + (uint32_t)krow * BSTR + (uint32_t)c8 * 16;

    float acc[4][4][4];
#pragma unroll
    for (int a = 0; a < 4; a++)
#pragma unroll
        for (int b = 0; b < 4; b++)
#pragma unroll
            for (int i = 0; i < 4; i++) acc[a][b][i] = 0.0f;

    const int KT = FDIM / 32;  // 128

#pragma unroll 1
    for (int s = 0; s < 2; s++) {
        const uint32_t st = sbase + s * STAGE;
        const size_t k0 = (size_t)s * 32;
        CPA16(st + adst, asrc + k0);
        CPA16(st + adst + 16, asrc + k0 + 8);
        CPA16(st + bdst0, bsrc + k0 * DDIM);
        CPA16(st + bdst0 + 128, bsrc + k0 * DDIM + 64);
        CPCOMMIT();
    }

#pragma unroll 1
    for (int c = 0; c < KT; c++) {
        CPWAIT1();
        __syncthreads();
        if (c + 2 < KT) {
            const uint32_t st = sbase + ((c + 2) % NSTG) * STAGE;
            const size_t k0 = (size_t)(c + 2) * 32;
            CPA16(st + adst, asrc + k0);
            CPA16(st + adst + 16, asrc + k0 + 8);
            CPA16(st + bdst0, bsrc + k0 * DDIM);
            CPA16(st + bdst0 + 128, bsrc + k0 * DDIM + 64);
        }
        CPCOMMIT();
        const uint32_t sA = sbase + (c % NSTG) * STAGE;
        const uint32_t sB = sA + A_SZ;
#pragma unroll
        for (int ks = 0; ks < 2; ks++) {
            uint32_t bfr[4][2];
#pragma unroll
            for (int hn = 0; hn < 2; hn++) {
                uint32_t r[4];
                ldsm4t(r, sB + (uint32_t)(ks * 16 + (grp & 1) * 8 + (lane & 7)) * BSTR +
                           (uint32_t)(wn * 32 + hn * 16 + (grp >> 1) * 8) * 2);
                bfr[hn * 2 + 0][0] = r[0]; bfr[hn * 2 + 0][1] = r[1];
                bfr[hn * 2 + 1][0] = r[2]; bfr[hn * 2 + 1][1] = r[3];
            }
#pragma unroll
            for (int mt = 0; mt < 4; mt++) {
                uint32_t afr[4];
                ldsm4(afr, sA + (uint32_t)(wm * 64 + mt * 16 + (grp & 1) * 8 + (lane & 7)) * ASTR +
                           (uint32_t)(ks * 16 + (grp >> 1) * 8) * 2);
#pragma unroll
                for (int nt = 0; nt < 4; nt++) mma16(acc[mt][nt], afr, bfr[nt]);
            }
        }
    }

    // epilogue: scale by routing weight -> g_y (fp32)
#pragma unroll
    for (int mt = 0; mt < 4; mt++) {
        const int r0 = pos_base + wm * 64 + mt * 16 + (lane >> 2);
        const int r1 = r0 + 8;
        const float w0 = (r0 < seg_end) ? g_row_w[r0] : 0.0f;
        const float w1 = (r1 < seg_end) ? g_row_w[r1] : 0.0f;
#pragma unroll
        for (int nt = 0; nt < 4; nt++) {
            const int n = n0 + wn * 32 + nt * 8 + 2 * (lane & 3);
            if (r0 < seg_end)
                *(float2*)(&g_y[(size_t)r0 * DDIM + n]) =
                    make_float2(w0 * acc[mt][nt][0], w0 * acc[mt][nt][1]);
            if (r1 < seg_end)
                *(float2*)(&g_y[(size_t)r1 * DDIM + n]) =
                    make_float2(w1 * acc[mt][nt][2], w1 * acc[mt][nt][3]);
        }
    }
}

// ---------------- combine: out[t] = y[pos(t,0)] + y[pos(t,1)] ----------------
__global__ void k_combine(float* __restrict__ out) {
    const int t = blockIdx.x;
    const int p0 = g_token_pos[t * 2 + 0];
    const int p1 = g_token_pos[t * 2 + 1];
    const float4* y0 = (const float4*)(g_y + (size_t)p0 * DDIM);
    const float4* y1 = (const float4*)(g_y + (size_t)p1 * DDIM);
    float4* o = (float4*)(out + (size_t)t * DDIM);
#pragma unroll
    for (int j = 0; j < 2; j++) {
        const int i = j * 256 + threadIdx.x;
        float4 a = y0[i];
        float4 b = y1[i];
        o[i] = make_float4(a.x + b.x, a.y + b.y, a.z + b.z, a.w + b.w);
    }
}

// ---------------- launch ----------------
extern "C" void kernel_launch(void* const* d_in, const int* in_sizes, int n_in,
                              void* d_out, int out_size) {
    (void)in_sizes; (void)n_in; (void)out_size;
    const float* hs = (const float*)d_in[0];
    const float* gw = (const float*)d_in[1];
    const float* wg = (const float*)d_in[2];
    const float* wu = (const float*)d_in[3];
    const float* wd = (const float*)d_in[4];
    float* out = (float*)d_out;

    __half* wg16p; cudaGetSymbolAddress((void**)&wg16p, g_wg16);
    __half* wu16p; cudaGetSymbolAddress((void**)&wu16p, g_wu16);
    __half* wd16p; cudaGetSymbolAddress((void**)&wd16p, g_wd16);

    cudaFuncSetAttribute(k_mlp1, cudaFuncAttributeMaxDynamicSharedMemorySize, DYNSM);
    cudaFuncSetAttribute(k_mlp2, cudaFuncAttributeMaxDynamicSharedMemorySize, DYNSM);

    k_cvtw<<<dim3(4096, 3), 256>>>((const float4*)wg, (const float4*)wu, (const float4*)wd,
                                   (uint2*)wg16p, (uint2*)wu16p, (uint2*)wd16p); // #1
    k_router<<<TTOK / 8, 256>>>(hs, gw);                                         // #2
    k_prep<<<1, 1024>>>();                                                       // #3
    k_mlp1<<<dim3(NPOS / 128, FDIM / 64, NEXP), 256, DYNSM>>>();                 // #4 (ncu slot)
    k_mlp2<<<dim3(NPOS / 128, DDIM / 128, NEXP), 256, DYNSM>>>();                // #5
    k_combine<<<TTOK, 256>>>(out);                                               // #6
}

// round 15
// speedup vs baseline: 1.3341x; 1.3341x over previous
#include <cuda_runtime.h>
#include <cuda_fp16.h>
#include <cstdint>
#include <cstddef>

#define TTOK 2048
#define DDIM 2048
#define FDIM 4096
#define NEXP 8
#define NPOS (TTOK * 2)
#define MAXTILE 48

#define ASTR 80                        // A smem row stride bytes (32 fp16 + 16B pad)
#define BSTR 272                       // B smem row stride bytes (128 fp16 + 16B pad)
#define A_SZ (128 * ASTR)              // 10240
#define B_SZ (32 * BSTR)               // 8704
#define STAGE (A_SZ + B_SZ)            // 18944
#define NSTG 3
#define DYNSM (NSTG * STAGE)           // 56832

// ---------------- scratch ----------------
__device__ int    g_offsets[NEXP + 1];
__device__ int    g_topk_idx[NPOS];
__device__ float  g_topk_w[NPOS];
__device__ int    g_row_token[NPOS];
__device__ float  g_row_w[NPOS];
__device__ int    g_token_pos[NPOS];
__device__ int    g_tile_e[MAXTILE];
__device__ int    g_tile_base[MAXTILE];
__device__ int    g_tile_cnt;
__device__ __half g_act[(size_t)NPOS * FDIM];
__device__ float  g_y[(size_t)NPOS * DDIM];
__device__ __half g_x16[(size_t)TTOK * DDIM];

// ---------------- helpers ----------------
__device__ __forceinline__ uint32_t smem_u32(const void* p) {
    uint32_t a;
    asm("{ .reg .u64 t; cvta.to.shared.u64 t, %1; cvt.u32.u64 %0, t; }" : "=r"(a) : "l"(p));
    return a;
}
__device__ __forceinline__ uint32_t pack2(float lo, float hi) {
    uint32_t r;
    asm("cvt.rn.f16x2.f32 %0, %1, %2;" : "=r"(r) : "f"(hi), "f"(lo));
    return r;
}
__device__ __forceinline__ void ldsm4(uint32_t* r, uint32_t a) {
    asm volatile("ldmatrix.sync.aligned.m8n8.x4.shared.b16 {%0,%1,%2,%3}, [%4];"
                 : "=r"(r[0]), "=r"(r[1]), "=r"(r[2]), "=r"(r[3]) : "r"(a));
}
__device__ __forceinline__ void ldsm4t(uint32_t* r, uint32_t a) {
    asm volatile("ldmatrix.sync.aligned.m8n8.x4.trans.shared.b16 {%0,%1,%2,%3}, [%4];"
                 : "=r"(r[0]), "=r"(r[1]), "=r"(r[2]), "=r"(r[3]) : "r"(a));
}
__device__ __forceinline__ void mma16(float* c, const uint32_t* a, const uint32_t* b) {
    asm volatile(
        "mma.sync.aligned.m16n8k16.row.col.f32.f16.f16.f32 "
        "{%0,%1,%2,%3},{%4,%5,%6,%7},{%8,%9},{%0,%1,%2,%3};"
        : "+f"(c[0]), "+f"(c[1]), "+f"(c[2]), "+f"(c[3])
        : "r"(a[0]), "r"(a[1]), "r"(a[2]), "r"(a[3]), "r"(b[0]), "r"(b[1]));
}
#define CPA16(dst, src) \
    asm volatile("cp.async.cg.shared.global [%0], [%1], 16;" :: "r"(dst), "l"(src))
#define CPCOMMIT() asm volatile("cp.async.commit_group;" ::: "memory")
#define CPWAIT1()  asm volatile("cp.async.wait_group 1;" ::: "memory")
#define STS128(a, v0, v1, v2, v3) \
    asm volatile("st.shared.v4.b32 [%0], {%1,%2,%3,%4};" :: "r"(a), "r"(v0), "r"(v1), "r"(v2), "r"(v3))

__device__ __forceinline__ float gelu_tanh(float x) {
    float x3 = x * x * x;
    return 0.5f * x * (1.0f + tanhf(0.7978845608028654f * (x + 0.044715f * x3)));
}

// ---------------- router (+ fused hs fp32->fp16 convert) ----------------
__global__ void k_router(const float* __restrict__ hs, const float* __restrict__ gw) {
    const int warp = threadIdx.x >> 5;
    const int lane = threadIdx.x & 31;
    const int t = blockIdx.x * 8 + warp;
    if (t >= TTOK) return;
    float acc[NEXP];
#pragma unroll
    for (int e = 0; e < NEXP; e++) acc[e] = 0.0f;
    const float2* hrow2 = (const float2*)(hs + (size_t)t * DDIM);
    uint32_t* xrow = (uint32_t*)(g_x16 + (size_t)t * DDIM);
    for (int i = lane; i < DDIM / 2; i += 32) {
        float2 x = hrow2[i];
        xrow[i] = pack2(x.x, x.y);
        const float* g0 = gw + (size_t)(2 * i) * NEXP;
#pragma unroll
        for (int e = 0; e < NEXP; e++)
            acc[e] = fmaf(x.x, g0[e], fmaf(x.y, g0[NEXP + e], acc[e]));
    }
#pragma unroll
    for (int e = 0; e < NEXP; e++) {
#pragma unroll
        for (int o = 16; o > 0; o >>= 1) acc[e] += __shfl_xor_sync(0xffffffffu, acc[e], o);
    }
    if (lane == 0) {
        float l[NEXP];
#pragma unroll
        for (int e = 0; e < NEXP; e++) l[e] = tanhf(acc[e] / 30.0f) * 30.0f;
        int i0 = 0;
#pragma unroll
        for (int e = 1; e < NEXP; e++) if (l[e] > l[i0]) i0 = e;
        int i1 = -1;
#pragma unroll
        for (int e = 0; e < NEXP; e++) {
            if (e == i0) continue;
            if (i1 < 0 || l[e] > l[i1]) i1 = e;
        }
        float ee = expf(l[i1] - l[i0]);
        g_topk_idx[t * 2 + 0] = i0;
        g_topk_idx[t * 2 + 1] = i1;
        g_topk_w[t * 2 + 0] = 1.0f / (1.0f + ee);
        g_topk_w[t * 2 + 1] = ee / (1.0f + ee);
    }
}

// ---------------- prep: counts + offsets + fill + compact tile map (one block) --------
__global__ void k_prep() {
    __shared__ int cnt[NEXP];
    __shared__ int fill[NEXP];
    const int tid = threadIdx.x;
    if (tid < NEXP) cnt[tid] = 0;
    __syncthreads();
    for (int i = tid; i < NPOS; i += blockDim.x) atomicAdd(&cnt[g_topk_idx[i]], 1);
    __syncthreads();
    if (tid == 0) {
        int o = 0;
        int nt = 0;
#pragma unroll
        for (int e = 0; e < NEXP; e++) {
            g_offsets[e] = o;
            fill[e] = o;
            const int seg = cnt[e];
            for (int b = 0; b < seg; b += 128) {
                g_tile_e[nt] = e;
                g_tile_base[nt] = o + b;
                nt++;
            }
            o += seg;
        }
        g_offsets[NEXP] = o;
        g_tile_cnt = nt;
    }
    __syncthreads();
    for (int i = tid; i < NPOS; i += blockDim.x) {
        const int e = g_topk_idx[i];
        const int pos = atomicAdd(&fill[e], 1);
        g_row_token[pos] = i >> 1;
        g_row_w[pos] = g_topk_w[i];
        g_token_pos[i] = pos;
    }
}

// ============ mlp1: act = gelu(X@Wg) * (X@Wu) ============
// 256 threads = 8 warps (2m x 4n), CTA tile 128x128 (64 gate + 64 up interleaved by 8 cols),
// K-chunk 32; A via cp.async, B via LDG fp32 + cvt + STS (conflict-free 128B-split stores).
// Grid x = compact tile index (expert + m-base via lookup), y = f-tile.
__global__ void __launch_bounds__(256, 2) k_mlp1(const float* __restrict__ wgf,
                                                 const float* __restrict__ wuf) {
    extern __shared__ uint8_t dsm[];
    if ((int)blockIdx.x >= g_tile_cnt) return;
    const int e = g_tile_e[blockIdx.x];
    const int pos_base = g_tile_base[blockIdx.x];
    const int seg_end = g_offsets[e + 1];
    const int f0 = blockIdx.y * 64;

    const uint32_t sbase = smem_u32(dsm);
    const int tid = threadIdx.x;
    const int lane = tid & 31;
    const int w = tid >> 5, wm = w & 1, wn = w >> 1;
    const int grp = lane >> 3;

    // A producer: row tid>>1 (0..127), half tid&1; per-row gathered token pointer
    int apos = pos_base + (tid >> 1);
    if (apos >= seg_end) apos = seg_end - 1;
    const __half* asrc = g_x16 + (size_t)g_row_token[apos] * DDIM + (tid & 1) * 16;
    const uint32_t adst = (uint32_t)(tid >> 1) * ASTR + (uint32_t)(tid & 1) * 32;

    // B producer: h = gate/up, krow = u>>2 (0..31), c = u&3.
    // Thread covers f-cols [8c,8c+8) and [8c+32,8c+40) of matrix h; stores 128B apart.
    const int h = tid >> 7;
    const int u = tid & 127;
    const int krow = u >> 2;
    const int c = u & 3;
    const float* bsrc0 = (h ? wuf : wgf) + (size_t)e * DDIM * FDIM + (size_t)krow * FDIM + f0 + c * 8;
    const uint32_t bdst0 = A_SZ + (uint32_t)krow * BSTR + (uint32_t)c * 32 + (uint32_t)h * 16;

    float acc[4][4][4];
#pragma unroll
    for (int a = 0; a < 4; a++)
#pragma unroll
        for (int b = 0; b < 4; b++)
#pragma unroll
            for (int i = 0; i < 4; i++) acc[a][b][i] = 0.0f;

    const int KT = DDIM / 32;  // 64
    float4 rb[4];

    // prologue: fill stages 0,1; preload regs for chunk 2
#pragma unroll 1
    for (int s = 0; s < 2; s++) {
        const uint32_t st = sbase + s * STAGE;
        const size_t k0 = (size_t)s * 32;
        rb[0] = *(const float4*)(bsrc0 + k0 * FDIM);
        rb[1] = *(const float4*)(bsrc0 + k0 * FDIM + 4);
        rb[2] = *(const float4*)(bsrc0 + k0 * FDIM + 32);
        rb[3] = *(const float4*)(bsrc0 + k0 * FDIM + 36);
        STS128(st + bdst0, pack2(rb[0].x, rb[0].y), pack2(rb[0].z, rb[0].w),
                           pack2(rb[1].x, rb[1].y), pack2(rb[1].z, rb[1].w));
        STS128(st + bdst0 + 128, pack2(rb[2].x, rb[2].y), pack2(rb[2].z, rb[2].w),
                                 pack2(rb[3].x, rb[3].y), pack2(rb[3].z, rb[3].w));
        CPA16(st + adst, asrc + k0);
        CPA16(st + adst + 16, asrc + k0 + 8);
        CPCOMMIT();
    }
    rb[0] = *(const float4*)(bsrc0 + (size_t)64 * FDIM);
    rb[1] = *(const float4*)(bsrc0 + (size_t)64 * FDIM + 4);
    rb[2] = *(const float4*)(bsrc0 + (size_t)64 * FDIM + 32);
    rb[3] = *(const float4*)(bsrc0 + (size_t)64 * FDIM + 36);

#pragma unroll 1
    for (int c2 = 0; c2 < KT; c2++) {
        CPWAIT1();
        __syncthreads();
        if (c2 + 2 < KT) {
            const uint32_t st = sbase + ((c2 + 2) % NSTG) * STAGE;
            const size_t k0 = (size_t)(c2 + 2) * 32;
            STS128(st + bdst0, pack2(rb[0].x, rb[0].y), pack2(rb[0].z, rb[0].w),
                               pack2(rb[1].x, rb[1].y), pack2(rb[1].z, rb[1].w));
            STS128(st + bdst0 + 128, pack2(rb[2].x, rb[2].y), pack2(rb[2].z, rb[2].w),
                                     pack2(rb[3].x, rb[3].y), pack2(rb[3].z, rb[3].w));
            CPA16(st + adst, asrc + k0);
            CPA16(st + adst + 16, asrc + k0 + 8);
        }
        CPCOMMIT();
        if (c2 + 3 < KT) {
            const size_t k0 = (size_t)(c2 + 3) * 32;
            rb[0] = *(const float4*)(bsrc0 + k0 * FDIM);
            rb[1] = *(const float4*)(bsrc0 + k0 * FDIM + 4);
            rb[2] = *(const float4*)(bsrc0 + k0 * FDIM + 32);
            rb[3] = *(const float4*)(bsrc0 + k0 * FDIM + 36);
        }
        // compute chunk c2
        const uint32_t sA = sbase + (c2 % NSTG) * STAGE;
        const uint32_t sB = sA + A_SZ;
#pragma unroll
        for (int ks = 0; ks < 2; ks++) {
            uint32_t bfr[4][2];
#pragma unroll
            for (int hn = 0; hn < 2; hn++) {
                uint32_t r[4];
                ldsm4t(r, sB + (uint32_t)(ks * 16 + (grp & 1) * 8 + (lane & 7)) * BSTR +
                           (uint32_t)(wn * 32 + hn * 16 + (grp >> 1) * 8) * 2);
                bfr[hn * 2 + 0][0] = r[0]; bfr[hn * 2 + 0][1] = r[1];
                bfr[hn * 2 + 1][0] = r[2]; bfr[hn * 2 + 1][1] = r[3];
            }
#pragma unroll
            for (int mt = 0; mt < 4; mt++) {
                uint32_t afr[4];
                ldsm4(afr, sA + (uint32_t)(wm * 64 + mt * 16 + (grp & 1) * 8 + (lane & 7)) * ASTR +
                           (uint32_t)(ks * 16 + (grp >> 1) * 8) * 2);
#pragma unroll
                for (int nt = 0; nt < 4; nt++) mma16(acc[mt][nt], afr, bfr[nt]);
            }
        }
    }

    // epilogue: nt even = gate, nt odd = up (same 8 f-cols)
#pragma unroll
    for (int mt = 0; mt < 4; mt++) {
        const int r0 = pos_base + wm * 64 + mt * 16 + (lane >> 2);
#pragma unroll
        for (int hn = 0; hn < 2; hn++) {
            const int fc = f0 + (wn * 2 + hn) * 8 + 2 * (lane & 3);
            const float* g = acc[mt][2 * hn];
            const float* uq = acc[mt][2 * hn + 1];
            if (r0 < seg_end)
                *(uint32_t*)(&g_act[(size_t)r0 * FDIM + fc]) =
                    pack2(gelu_tanh(g[0]) * uq[0], gelu_tanh(g[1]) * uq[1]);
            if (r0 + 8 < seg_end)
                *(uint32_t*)(&g_act[(size_t)(r0 + 8) * FDIM + fc]) =
                    pack2(gelu_tanh(g[2]) * uq[2], gelu_tanh(g[3]) * uq[3]);
        }
    }
}

// ============ mlp2: y = w * (act @ Wd) ============
__global__ void __launch_bounds__(256, 2) k_mlp2(const float* __restrict__ wdf) {
    extern __shared__ uint8_t dsm[];
    if ((int)blockIdx.x >= g_tile_cnt) return;
    const int e = g_tile_e[blockIdx.x];
    const int pos_base = g_tile_base[blockIdx.x];
    const int seg_end = g_offsets[e + 1];
    const int n0 = blockIdx.y * 128;

    const uint32_t sbase = smem_u32(dsm);
    const int tid = threadIdx.x;
    const int lane = tid & 31;
    const int w = tid >> 5, wm = w & 1, wn = w >> 1;
    const int grp = lane >> 3;

    int apos = pos_base + (tid >> 1);
    if (apos >= seg_end) apos = seg_end - 1;
    const __half* asrc = g_act + (size_t)apos * FDIM + (tid & 1) * 16;
    const uint32_t adst = (uint32_t)(tid >> 1) * ASTR + (uint32_t)(tid & 1) * 32;

    const int krow = tid >> 3;           // 0..31
    const int c8 = tid & 7;              // 8-col group
    const float* bsrc0 = wdf + (size_t)e * FDIM * DDIM + (size_t)krow * DDIM + n0 + c8 * 8;
    const uint32_t bdst0 = A_SZ + (uint32_t)krow * BSTR + (uint32_t)c8 * 16;

    float acc[4][4][4];
#pragma unroll
    for (int a = 0; a < 4; a++)
#pragma unroll
        for (int b = 0; b < 4; b++)
#pragma unroll
            for (int i = 0; i < 4; i++) acc[a][b][i] = 0.0f;

    const int KT = FDIM / 32;  // 128
    float4 rb[4];

#pragma unroll 1
    for (int s = 0; s < 2; s++) {
        const uint32_t st = sbase + s * STAGE;
        const size_t k0 = (size_t)s * 32;
        rb[0] = *(const float4*)(bsrc0 + k0 * DDIM);
        rb[1] = *(const float4*)(bsrc0 + k0 * DDIM + 4);
        rb[2] = *(const float4*)(bsrc0 + k0 * DDIM + 64);
        rb[3] = *(const float4*)(bsrc0 + k0 * DDIM + 68);
        STS128(st + bdst0, pack2(rb[0].x, rb[0].y), pack2(rb[0].z, rb[0].w),
                           pack2(rb[1].x, rb[1].y), pack2(rb[1].z, rb[1].w));
        STS128(st + bdst0 + 128, pack2(rb[2].x, rb[2].y), pack2(rb[2].z, rb[2].w),
                                 pack2(rb[3].x, rb[3].y), pack2(rb[3].z, rb[3].w));
        CPA16(st + adst, asrc + k0);
        CPA16(st + adst + 16, asrc + k0 + 8);
        CPCOMMIT();
    }
    rb[0] = *(const float4*)(bsrc0 + (size_t)64 * DDIM);
    rb[1] = *(const float4*)(bsrc0 + (size_t)64 * DDIM + 4);
    rb[2] = *(const float4*)(bsrc0 + (size_t)64 * DDIM + 64);
    rb[3] = *(const float4*)(bsrc0 + (size_t)64 * DDIM + 68);

#pragma unroll 1
    for (int c = 0; c < KT; c++) {
        CPWAIT1();
        __syncthreads();
        if (c + 2 < KT) {
            const uint32_t st = sbase + ((c + 2) % NSTG) * STAGE;
            const size_t k0 = (size_t)(c + 2) * 32;
            STS128(st + bdst0, pack2(rb[0].x, rb[0].y), pack2(rb[0].z, rb[0].w),
                               pack2(rb[1].x, rb[1].y), pack2(rb[1].z, rb[1].w));
            STS128(st + bdst0 + 128, pack2(rb[2].x, rb[2].y), pack2(rb[2].z, rb[2].w),
                                     pack2(rb[3].x, rb[3].y), pack2(rb[3].z, rb[3].w));
            CPA16(st + adst, asrc + k0);
            CPA16(st + adst + 16, asrc + k0 + 8);
        }
        CPCOMMIT();
        if (c + 3 < KT) {
            const size_t k0 = (size_t)(c + 3) * 32;
            rb[0] = *(const float4*)(bsrc0 + k0 * DDIM);
            rb[1] = *(const float4*)(bsrc0 + k0 * DDIM + 4);
            rb[2] = *(const float4*)(bsrc0 + k0 * DDIM + 64);
            rb[3] = *(const float4*)(bsrc0 + k0 * DDIM + 68);
        }
        const uint32_t sA = sbase + (c % NSTG) * STAGE;
        const uint32_t sB = sA + A_SZ;
#pragma unroll
        for (int ks = 0; ks < 2; ks++) {
            uint32_t bfr[4][2];
#pragma unroll
            for (int hn = 0; hn < 2; hn++) {
                uint32_t r[4];
                ldsm4t(r, sB + (uint32_t)(ks * 16 + (grp & 1) * 8 + (lane & 7)) * BSTR +
                           (uint32_t)(wn * 32 + hn * 16 + (grp >> 1) * 8) * 2);
                bfr[hn * 2 + 0][0] = r[0]; bfr[hn * 2 + 0][1] = r[1];
                bfr[hn * 2 + 1][0] = r[2]; bfr[hn * 2 + 1][1] = r[3];
            }
#pragma unroll
            for (int mt = 0; mt < 4; mt++) {
                uint32_t afr[4];
                ldsm4(afr, sA + (uint32_t)(wm * 64 + mt * 16 + (grp & 1) * 8 + (lane & 7)) * ASTR +
                           (uint32_t)(ks * 16 + (grp >> 1) * 8) * 2);
#pragma unroll
                for (int nt = 0; nt < 4; nt++) mma16(acc[mt][nt], afr, bfr[nt]);
            }
        }
    }

    // epilogue: scale by routing weight -> g_y (fp32)
#pragma unroll
    for (int mt = 0; mt < 4; mt++) {
        const int r0 = pos_base + wm * 64 + mt * 16 + (lane >> 2);
        const int r1 = r0 + 8;
        const float w0 = (r0 < seg_end) ? g_row_w[r0] : 0.0f;
        const float w1 = (r1 < seg_end) ? g_row_w[r1] : 0.0f;
#pragma unroll
        for (int nt = 0; nt < 4; nt++) {
            const int n = n0 + wn * 32 + nt * 8 + 2 * (lane & 3);
            if (r0 < seg_end)
                *(float2*)(&g_y[(size_t)r0 * DDIM + n]) =
                    make_float2(w0 * acc[mt][nt][0], w0 * acc[mt][nt][1]);
            if (r1 < seg_end)
                *(float2*)(&g_y[(size_t)r1 * DDIM + n]) =
                    make_float2(w1 * acc[mt][nt][2], w1 * acc[mt][nt][3]);
        }
    }
}

// ---------------- combine: out[t] = y[pos(t,0)] + y[pos(t,1)] ----------------
__global__ void k_combine(float* __restrict__ out) {
    const int t = blockIdx.x;
    const int p0 = g_token_pos[t * 2 + 0];
    const int p1 = g_token_pos[t * 2 + 1];
    const float4* y0 = (const float4*)(g_y + (size_t)p0 * DDIM);
    const float4* y1 = (const float4*)(g_y + (size_t)p1 * DDIM);
    float4* o = (float4*)(out + (size_t)t * DDIM);
#pragma unroll
    for (int j = 0; j < 2; j++) {
        const int i = j * 256 + threadIdx.x;
        float4 a = y0[i];
        float4 b = y1[i];
        o[i] = make_float4(a.x + b.x, a.y + b.y, a.z + b.z, a.w + b.w);
    }
}

// ---------------- launch ----------------
extern "C" void kernel_launch(void* const* d_in, const int* in_sizes, int n_in,
                              void* d_out, int out_size) {
    (void)in_sizes; (void)n_in; (void)out_size;
    const float* hs = (const float*)d_in[0];
    const float* gw = (const float*)d_in[1];
    const float* wg = (const float*)d_in[2];
    const float* wu = (const float*)d_in[3];
    const float* wd = (const float*)d_in[4];
    float* out = (float*)d_out;

    cudaFuncSetAttribute(k_mlp1, cudaFuncAttributeMaxDynamicSharedMemorySize, DYNSM);
    cudaFuncSetAttribute(k_mlp2, cudaFuncAttributeMaxDynamicSharedMemorySize, DYNSM);

    k_router<<<TTOK / 8, 256>>>(hs, gw);                                // #1 (also converts hs->fp16)
    k_prep<<<1, 1024>>>();                                              // #2 (scan+assign+tile map)
    k_mlp1<<<dim3(MAXTILE, FDIM / 64, 1), 256, DYNSM>>>(wg, wu);        // #3
    k_mlp2<<<dim3(MAXTILE, DDIM / 128, 1), 256, DYNSM>>>(wd);           // #4
    k_combine<<<TTOK, 256>>>(out);                                      // #5
}

// round 16
// speedup vs baseline: 1.3372x; 1.0023x over previous
#include <cuda_runtime.h>
#include <cuda_fp16.h>
#include <cstdint>
#include <cstddef>

#define TTOK 2048
#define DDIM 2048
#define FDIM 4096
#define NEXP 8
#define NPOS (TTOK * 2)
#define MAXTILE 48

#define ASTR 80                        // A smem row stride bytes (32 fp16 + 16B pad)
#define BSTR 272                       // B smem row stride bytes (128 fp16 + 16B pad)
#define A_SZ (128 * ASTR)              // 10240
#define B_SZ (32 * BSTR)               // 8704
#define STAGE (A_SZ + B_SZ)            // 18944
#define NSTG 3
#define DYNSM (NSTG * STAGE)           // 56832

// ---------------- scratch ----------------
__device__ int    g_offsets[NEXP + 1];
__device__ int    g_topk_idx[NPOS];
__device__ float  g_topk_w[NPOS];
__device__ int    g_row_token[NPOS];
__device__ float  g_row_w[NPOS];
__device__ int    g_token_pos[NPOS];
__device__ int    g_tile_e[MAXTILE];
__device__ int    g_tile_base[MAXTILE];
__device__ int    g_tile_cnt;
__device__ __half g_act[(size_t)NPOS * FDIM];
__device__ float  g_y[(size_t)NPOS * DDIM];
__device__ __half g_x16[(size_t)TTOK * DDIM];

// ---------------- helpers ----------------
__device__ __forceinline__ uint32_t smem_u32(const void* p) {
    uint32_t a;
    asm("{ .reg .u64 t; cvta.to.shared.u64 t, %1; cvt.u32.u64 %0, t; }" : "=r"(a) : "l"(p));
    return a;
}
__device__ __forceinline__ uint32_t pack2(float lo, float hi) {
    uint32_t r;
    asm("cvt.rn.f16x2.f32 %0, %1, %2;" : "=r"(r) : "f"(hi), "f"(lo));
    return r;
}
__device__ __forceinline__ void ldsm4(uint32_t* r, uint32_t a) {
    asm volatile("ldmatrix.sync.aligned.m8n8.x4.shared.b16 {%0,%1,%2,%3}, [%4];"
                 : "=r"(r[0]), "=r"(r[1]), "=r"(r[2]), "=r"(r[3]) : "r"(a));
}
__device__ __forceinline__ void ldsm4t(uint32_t* r, uint32_t a) {
    asm volatile("ldmatrix.sync.aligned.m8n8.x4.trans.shared.b16 {%0,%1,%2,%3}, [%4];"
                 : "=r"(r[0]), "=r"(r[1]), "=r"(r[2]), "=r"(r[3]) : "r"(a));
}
__device__ __forceinline__ void mma16(float* c, const uint32_t* a, const uint32_t* b) {
    asm volatile(
        "mma.sync.aligned.m16n8k16.row.col.f32.f16.f16.f32 "
        "{%0,%1,%2,%3},{%4,%5,%6,%7},{%8,%9},{%0,%1,%2,%3};"
        : "+f"(c[0]), "+f"(c[1]), "+f"(c[2]), "+f"(c[3])
        : "r"(a[0]), "r"(a[1]), "r"(a[2]), "r"(a[3]), "r"(b[0]), "r"(b[1]));
}
#define CPA16(dst, src) \
    asm volatile("cp.async.cg.shared.global [%0], [%1], 16;" :: "r"(dst), "l"(src))
#define CPCOMMIT() asm volatile("cp.async.commit_group;" ::: "memory")
#define CPWAIT1()  asm volatile("cp.async.wait_group 1;" ::: "memory")
#define STS128(a, v0, v1, v2, v3) \
    asm volatile("st.shared.v4.b32 [%0], {%1,%2,%3,%4};" :: "r"(a), "r"(v0), "r"(v1), "r"(v2), "r"(v3))

__device__ __forceinline__ float gelu_tanh(float x) {
    float x3 = x * x * x;
    return 0.5f * x * (1.0f + tanhf(0.7978845608028654f * (x + 0.044715f * x3)));
}

// ---------------- router (+ fused hs fp32->fp16 convert) ----------------
__global__ void k_router(const float* __restrict__ hs, const float* __restrict__ gw) {
    const int warp = threadIdx.x >> 5;
    const int lane = threadIdx.x & 31;
    const int t = blockIdx.x * 8 + warp;
    if (t >= TTOK) return;
    float acc[NEXP];
#pragma unroll
    for (int e = 0; e < NEXP; e++) acc[e] = 0.0f;
    const float2* hrow2 = (const float2*)(hs + (size_t)t * DDIM);
    uint32_t* xrow = (uint32_t*)(g_x16 + (size_t)t * DDIM);
    for (int i = lane; i < DDIM / 2; i += 32) {
        float2 x = hrow2[i];
        xrow[i] = pack2(x.x, x.y);
        const float* g0 = gw + (size_t)(2 * i) * NEXP;
#pragma unroll
        for (int e = 0; e < NEXP; e++)
            acc[e] = fmaf(x.x, g0[e], fmaf(x.y, g0[NEXP + e], acc[e]));
    }
#pragma unroll
    for (int e = 0; e < NEXP; e++) {
#pragma unroll
        for (int o = 16; o > 0; o >>= 1) acc[e] += __shfl_xor_sync(0xffffffffu, acc[e], o);
    }
    if (lane == 0) {
        float l[NEXP];
#pragma unroll
        for (int e = 0; e < NEXP; e++) l[e] = tanhf(acc[e] / 30.0f) * 30.0f;
        int i0 = 0;
#pragma unroll
        for (int e = 1; e < NEXP; e++) if (l[e] > l[i0]) i0 = e;
        int i1 = -1;
#pragma unroll
        for (int e = 0; e < NEXP; e++) {
            if (e == i0) continue;
            if (i1 < 0 || l[e] > l[i1]) i1 = e;
        }
        float ee = expf(l[i1] - l[i0]);
        g_topk_idx[t * 2 + 0] = i0;
        g_topk_idx[t * 2 + 1] = i1;
        g_topk_w[t * 2 + 0] = 1.0f / (1.0f + ee);
        g_topk_w[t * 2 + 1] = ee / (1.0f + ee);
    }
}

// ---------------- prep: counts + offsets + fill + compact tile map (one block) --------
__global__ void k_prep() {
    __shared__ int cnt[NEXP];
    __shared__ int fill[NEXP];
    const int tid = threadIdx.x;
    if (tid < NEXP) cnt[tid] = 0;
    __syncthreads();
    for (int i = tid; i < NPOS; i += blockDim.x) atomicAdd(&cnt[g_topk_idx[i]], 1);
    __syncthreads();
    if (tid == 0) {
        int o = 0;
        int nt = 0;
#pragma unroll
        for (int e = 0; e < NEXP; e++) {
            g_offsets[e] = o;
            fill[e] = o;
            const int seg = cnt[e];
            for (int b = 0; b < seg; b += 128) {
                g_tile_e[nt] = e;
                g_tile_base[nt] = o + b;
                nt++;
            }
            o += seg;
        }
        g_offsets[NEXP] = o;
        g_tile_cnt = nt;
    }
    __syncthreads();
    for (int i = tid; i < NPOS; i += blockDim.x) {
        const int e = g_topk_idx[i];
        const int pos = atomicAdd(&fill[e], 1);
        g_row_token[pos] = i >> 1;
        g_row_w[pos] = g_topk_w[i];
        g_token_pos[i] = pos;
    }
}

// ============ mlp1: act = gelu(X@Wg) * (X@Wu) ============
// 256 threads = 8 warps (2m x 4n), CTA tile 128x128 (64 gate + 64 up interleaved by 8 cols),
// K-chunk 32; A via cp.async, B via LDG fp32 + cvt + STS (conflict-free 128B-split stores).
// Grid x = compact tile index (expert + m-base via lookup), y = f-tile.
__global__ void __launch_bounds__(256, 2) k_mlp1(const float* __restrict__ wgf,
                                                 const float* __restrict__ wuf) {
    extern __shared__ uint8_t dsm[];
    if ((int)blockIdx.x >= g_tile_cnt) return;
    const int e = g_tile_e[blockIdx.x];
    const int pos_base = g_tile_base[blockIdx.x];
    const int seg_end = g_offsets[e + 1];
    const int f0 = blockIdx.y * 64;

    const uint32_t sbase = smem_u32(dsm);
    const int tid = threadIdx.x;
    const int lane = tid & 31;
    const int w = tid >> 5, wm = w & 1, wn = w >> 1;
    const int grp = lane >> 3;

    // A producer: row tid>>1 (0..127), half tid&1; per-row gathered token pointer
    int apos = pos_base + (tid >> 1);
    if (apos >= seg_end) apos = seg_end - 1;
    const __half* asrc = g_x16 + (size_t)g_row_token[apos] * DDIM + (tid & 1) * 16;
    const uint32_t adst = (uint32_t)(tid >> 1) * ASTR + (uint32_t)(tid & 1) * 32;

    // B producer: h = gate/up, krow = u>>2 (0..31), c = u&3.
    // Thread covers f-cols [8c,8c+8) and [8c+32,8c+40) of matrix h; stores 128B apart.
    const int h = tid >> 7;
    const int u = tid & 127;
    const int krow = u >> 2;
    const int c = u & 3;
    const float* bsrc0 = (h ? wuf : wgf) + (size_t)e * DDIM * FDIM + (size_t)krow * FDIM + f0 + c * 8;
    const uint32_t bdst0 = A_SZ + (uint32_t)krow * BSTR + (uint32_t)c * 32 + (uint32_t)h * 16;

    float acc[4][4][4];
#pragma unroll
    for (int a = 0; a < 4; a++)
#pragma unroll
        for (int b = 0; b < 4; b++)
#pragma unroll
            for (int i = 0; i < 4; i++) acc[a][b][i] = 0.0f;

    const int KT = DDIM / 32;  // 64
    float4 rb[4];

    // prologue: fill stages 0,1; preload regs for chunk 2
#pragma unroll 1
    for (int s = 0; s < 2; s++) {
        const uint32_t st = sbase + s * STAGE;
        const size_t k0 = (size_t)s * 32;
        rb[0] = *(const float4*)(bsrc0 + k0 * FDIM);
        rb[1] = *(const float4*)(bsrc0 + k0 * FDIM + 4);
        rb[2] = *(const float4*)(bsrc0 + k0 * FDIM + 32);
        rb[3] = *(const float4*)(bsrc0 + k0 * FDIM + 36);
        STS128(st + bdst0, pack2(rb[0].x, rb[0].y), pack2(rb[0].z, rb[0].w),
                           pack2(rb[1].x, rb[1].y), pack2(rb[1].z, rb[1].w));
        STS128(st + bdst0 + 128, pack2(rb[2].x, rb[2].y), pack2(rb[2].z, rb[2].w),
                                 pack2(rb[3].x, rb[3].y), pack2(rb[3].z, rb[3].w));
        CPA16(st + adst, asrc + k0);
        CPA16(st + adst + 16, asrc + k0 + 8);
        CPCOMMIT();
    }
    rb[0] = *(const float4*)(bsrc0 + (size_t)64 * FDIM);
    rb[1] = *(const float4*)(bsrc0 + (size_t)64 * FDIM + 4);
    rb[2] = *(const float4*)(bsrc0 + (size_t)64 * FDIM + 32);
    rb[3] = *(const float4*)(bsrc0 + (size_t)64 * FDIM + 36);

#pragma unroll 1
    for (int c2 = 0; c2 < KT; c2++) {
        CPWAIT1();
        __syncthreads();
        if (c2 + 2 < KT) {
            const uint32_t st = sbase + ((c2 + 2) % NSTG) * STAGE;
            const size_t k0 = (size_t)(c2 + 2) * 32;
            STS128(st + bdst0, pack2(rb[0].x, rb[0].y), pack2(rb[0].z, rb[0].w),
                               pack2(rb[1].x, rb[1].y), pack2(rb[1].z, rb[1].w));
            STS128(st + bdst0 + 128, pack2(rb[2].x, rb[2].y), pack2(rb[2].z, rb[2].w),
                                     pack2(rb[3].x, rb[3].y), pack2(rb[3].z, rb[3].w));
            CPA16(st + adst, asrc + k0);
            CPA16(st + adst + 16, asrc + k0 + 8);
        }
        CPCOMMIT();
        if (c2 + 3 < KT) {
            const size_t k0 = (size_t)(c2 + 3) * 32;
            rb[0] = *(const float4*)(bsrc0 + k0 * FDIM);
            rb[1] = *(const float4*)(bsrc0 + k0 * FDIM + 4);
            rb[2] = *(const float4*)(bsrc0 + k0 * FDIM + 32);
            rb[3] = *(const float4*)(bsrc0 + k0 * FDIM + 36);
        }
        // compute chunk c2
        const uint32_t sA = sbase + (c2 % NSTG) * STAGE;
        const uint32_t sB = sA + A_SZ;
#pragma unroll
        for (int ks = 0; ks < 2; ks++) {
            uint32_t bfr[4][2];
#pragma unroll
            for (int hn = 0; hn < 2; hn++) {
                uint32_t r[4];
                ldsm4t(r, sB + (uint32_t)(ks * 16 + (grp & 1) * 8 + (lane & 7)) * BSTR +
                           (uint32_t)(wn * 32 + hn * 16 + (grp >> 1) * 8) * 2);
                bfr[hn * 2 + 0][0] = r[0]; bfr[hn * 2 + 0][1] = r[1];
                bfr[hn * 2 + 1][0] = r[2]; bfr[hn * 2 + 1][1] = r[3];
            }
#pragma unroll
            for (int mt = 0; mt < 4; mt++) {
                uint32_t afr[4];
                ldsm4(afr, sA + (uint32_t)(wm * 64 + mt * 16 + (grp & 1) * 8 + (lane & 7)) * ASTR +
                           (uint32_t)(ks * 16 + (grp >> 1) * 8) * 2);
#pragma unroll
                for (int nt = 0; nt < 4; nt++) mma16(acc[mt][nt], afr, bfr[nt]);
            }
        }
    }

    // epilogue: nt even = gate, nt odd = up (same 8 f-cols)
#pragma unroll
    for (int mt = 0; mt < 4; mt++) {
        const int r0 = pos_base + wm * 64 + mt * 16 + (lane >> 2);
#pragma unroll
        for (int hn = 0; hn < 2; hn++) {
            const int fc = f0 + (wn * 2 + hn) * 8 + 2 * (lane & 3);
            const float* g = acc[mt][2 * hn];
            const float* uq = acc[mt][2 * hn + 1];
            if (r0 < seg_end)
                *(uint32_t*)(&g_act[(size_t)r0 * FDIM + fc]) =
                    pack2(gelu_tanh(g[0]) * uq[0], gelu_tanh(g[1]) * uq[1]);
            if (r0 + 8 < seg_end)
                *(uint32_t*)(&g_act[(size_t)(r0 + 8) * FDIM + fc]) =
                    pack2(gelu_tanh(g[2]) * uq[2], gelu_tanh(g[3]) * uq[3]);
        }
    }
}

// ============ mlp2: y = w * (act @ Wd) ============
__global__ void __launch_bounds__(256, 2) k_mlp2(const float* __restrict__ wdf) {
    extern __shared__ uint8_t dsm[];
    if ((int)blockIdx.x >= g_tile_cnt) return;
    const int e = g_tile_e[blockIdx.x];
    const int pos_base = g_tile_base[blockIdx.x];
    const int seg_end = g_offsets[e + 1];
    const int n0 = blockIdx.y * 128;

    const uint32_t sbase = smem_u32(dsm);
    const int tid = threadIdx.x;
    const int lane = tid & 31;
    const int w = tid >> 5, wm = w & 1, wn = w >> 1;
    const int grp = lane >> 3;

    int apos = pos_base + (tid >> 1);
    if (apos >= seg_end) apos = seg_end - 1;
    const __half* asrc = g_act + (size_t)apos * FDIM + (tid & 1) * 16;
    const uint32_t adst = (uint32_t)(tid >> 1) * ASTR + (uint32_t)(tid & 1) * 32;

    const int krow = tid >> 3;           // 0..31
    const int c8 = tid & 7;              // 8-col group
    const float* bsrc0 = wdf + (size_t)e * FDIM * DDIM + (size_t)krow * DDIM + n0 + c8 * 8;
    const uint32_t bdst0 = A_SZ + (uint32_t)krow * BSTR + (uint32_t)c8 * 16;

    float acc[4][4][4];
#pragma unroll
    for (int a = 0; a < 4; a++)
#pragma unroll
        for (int b = 0; b < 4; b++)
#pragma unroll
            for (int i = 0; i < 4; i++) acc[a][b][i] = 0.0f;

    const int KT = FDIM / 32;  // 128
    float4 rb[4];

#pragma unroll 1
    for (int s = 0; s < 2; s++) {
        const uint32_t st = sbase + s * STAGE;
        const size_t k0 = (size_t)s * 32;
        rb[0] = *(const float4*)(bsrc0 + k0 * DDIM);
        rb[1] = *(const float4*)(bsrc0 + k0 * DDIM + 4);
        rb[2] = *(const float4*)(bsrc0 + k0 * DDIM + 64);
        rb[3] = *(const float4*)(bsrc0 + k0 * DDIM + 68);
        STS128(st + bdst0, pack2(rb[0].x, rb[0].y), pack2(rb[0].z, rb[0].w),
                           pack2(rb[1].x, rb[1].y), pack2(rb[1].z, rb[1].w));
        STS128(st + bdst0 + 128, pack2(rb[2].x, rb[2].y), pack2(rb[2].z, rb[2].w),
                                 pack2(rb[3].x, rb[3].y), pack2(rb[3].z, rb[3].w));
        CPA16(st + adst, asrc + k0);
        CPA16(st + adst + 16, asrc + k0 + 8);
        CPCOMMIT();
    }
    rb[0] = *(const float4*)(bsrc0 + (size_t)64 * DDIM);
    rb[1] = *(const float4*)(bsrc0 + (size_t)64 * DDIM + 4);
    rb[2] = *(const float4*)(bsrc0 + (size_t)64 * DDIM + 64);
    rb[3] = *(const float4*)(bsrc0 + (size_t)64 * DDIM + 68);

#pragma unroll 1
    for (int c = 0; c < KT; c++) {
        CPWAIT1();
        __syncthreads();
        if (c + 2 < KT) {
            const uint32_t st = sbase + ((c + 2) % NSTG) * STAGE;
            const size_t k0 = (size_t)(c + 2) * 32;
            STS128(st + bdst0, pack2(rb[0].x, rb[0].y), pack2(rb[0].z, rb[0].w),
                               pack2(rb[1].x, rb[1].y), pack2(rb[1].z, rb[1].w));
            STS128(st + bdst0 + 128, pack2(rb[2].x, rb[2].y), pack2(rb[2].z, rb[2].w),
                                     pack2(rb[3].x, rb[3].y), pack2(rb[3].z, rb[3].w));
            CPA16(st + adst, asrc + k0);
            CPA16(st + adst + 16, asrc + k0 + 8);
        }
        CPCOMMIT();
        if (c + 3 < KT) {
            const size_t k0 = (size_t)(c + 3) * 32;
            rb[0] = *(const float4*)(bsrc0 + k0 * DDIM);
            rb[1] = *(const float4*)(bsrc0 + k0 * DDIM + 4);
            rb[2] = *(const float4*)(bsrc0 + k0 * DDIM + 64);
            rb[3] = *(const float4*)(bsrc0 + k0 * DDIM + 68);
        }
        const uint32_t sA = sbase + (c % NSTG) * STAGE;
        const uint32_t sB = sA + A_SZ;
#pragma unroll
        for (int ks = 0; ks < 2; ks++) {
            uint32_t bfr[4][2];
#pragma unroll
            for (int hn = 0; hn < 2; hn++) {
                uint32_t r[4];
                ldsm4t(r, sB + (uint32_t)(ks * 16 + (grp & 1) * 8 + (lane & 7)) * BSTR +
                           (uint32_t)(wn * 32 + hn * 16 + (grp >> 1) * 8) * 2);
                bfr[hn * 2 + 0][0] = r[0]; bfr[hn * 2 + 0][1] = r[1];
                bfr[hn * 2 + 1][0] = r[2]; bfr[hn * 2 + 1][1] = r[3];
            }
#pragma unroll
            for (int mt = 0; mt < 4; mt++) {
                uint32_t afr[4];
                ldsm4(afr, sA + (uint32_t)(wm * 64 + mt * 16 + (grp & 1) * 8 + (lane & 7)) * ASTR +
                           (uint32_t)(ks * 16 + (grp >> 1) * 8) * 2);
#pragma unroll
                for (int nt = 0; nt < 4; nt++) mma16(acc[mt][nt], afr, bfr[nt]);
            }
        }
    }

    // epilogue: scale by routing weight -> g_y (fp32)
#pragma unroll
    for (int mt = 0; mt < 4; mt++) {
        const int r0 = pos_base + wm * 64 + mt * 16 + (lane >> 2);
        const int r1 = r0 + 8;
        const float w0 = (r0 < seg_end) ? g_row_w[r0] : 0.0f;
        const float w1 = (r1 < seg_end) ? g_row_w[r1] : 0.0f;
#pragma unroll
        for (int nt = 0; nt < 4; nt++) {
            const int n = n0 + wn * 32 + nt * 8 + 2 * (lane & 3);
            if (r0 < seg_end)
                *(float2*)(&g_y[(size_t)r0 * DDIM + n]) =
                    make_float2(w0 * acc[mt][nt][0], w0 * acc[mt][nt][1]);
            if (r1 < seg_end)
                *(float2*)(&g_y[(size_t)r1 * DDIM + n]) =
                    make_float2(w1 * acc[mt][nt][2], w1 * acc[mt][nt][3]);
        }
    }
}

// ---------------- combine: out[t] = y[pos(t,0)] + y[pos(t,1)], 2 tokens/block ---------
__global__ void k_combine(float* __restrict__ out) {
#pragma unroll
    for (int s = 0; s < 2; s++) {
        const int t = blockIdx.x * 2 + s;
        const int p0 = g_token_pos[t * 2 + 0];
        const int p1 = g_token_pos[t * 2 + 1];
        const float4* y0 = (const float4*)(g_y + (size_t)p0 * DDIM);
        const float4* y1 = (const float4*)(g_y + (size_t)p1 * DDIM);
        float4* o = (float4*)(out + (size_t)t * DDIM);
#pragma unroll
        for (int j = 0; j < 2; j++) {
            const int i = j * 256 + threadIdx.x;
            float4 a = y0[i];
            float4 b = y1[i];
            o[i] = make_float4(a.x + b.x, a.y + b.y, a.z + b.z, a.w + b.w);
        }
    }
}

// ---------------- launch ----------------
extern "C" void kernel_launch(void* const* d_in, const int* in_sizes, int n_in,
                              void* d_out, int out_size) {
    (void)in_sizes; (void)n_in; (void)out_size;
    const float* hs = (const float*)d_in[0];
    const float* gw = (const float*)d_in[1];
    const float* wg = (const float*)d_in[2];
    const float* wu = (const float*)d_in[3];
    const float* wd = (const float*)d_in[4];
    float* out = (float*)d_out;

    cudaFuncSetAttribute(k_mlp1, cudaFuncAttributeMaxDynamicSharedMemorySize, DYNSM);
    cudaFuncSetAttribute(k_mlp2, cudaFuncAttributeMaxDynamicSharedMemorySize, DYNSM);

    k_router<<<TTOK / 8, 256>>>(hs, gw);                                // #1 (also converts hs->fp16)
    k_prep<<<1, 1024>>>();                                              // #2 (scan+assign+tile map)
    k_mlp1<<<dim3(MAXTILE, FDIM / 64, 1), 256, DYNSM>>>(wg, wu);        // #3
    k_mlp2<<<dim3(MAXTILE, DDIM / 128, 1), 256, DYNSM>>>(wd);           // #4
    k_combine<<<TTOK / 2, 256>>>(out);                                  // #5
}

// round 17
// speedup vs baseline: 1.3518x; 1.0109x over previous
#include <cuda_runtime.h>
#include <cuda_fp16.h>
#include <cstdint>
#include <cstddef>

#define TTOK 2048
#define DDIM 2048
#define FDIM 4096
#define NEXP 8
#define NPOS (TTOK * 2)
#define MAXTILE 48

#define ASTR 80                        // A smem row stride bytes (32 fp16 + 16B pad)
#define BSTR 272                       // B smem row stride bytes (128 fp16 + 16B pad)
#define A_SZ (128 * ASTR)              // 10240
#define B_SZ (32 * BSTR)               // 8704
#define STAGE (A_SZ + B_SZ)            // 18944
#define NSTG 3
#define DYNSM (NSTG * STAGE)           // 56832

// ---------------- scratch ----------------
__device__ int    g_offsets[NEXP + 1];
__device__ int    g_topk_idx[NPOS];
__device__ float  g_topk_w[NPOS];
__device__ int    g_row_token[NPOS];
__device__ float  g_row_w[NPOS];
__device__ int    g_tile_e[MAXTILE];
__device__ int    g_tile_base[MAXTILE];
__device__ int    g_tile_cnt;
__device__ __half g_act[(size_t)NPOS * FDIM];
__device__ __half g_x16[(size_t)TTOK * DDIM];

// ---------------- helpers ----------------
__device__ __forceinline__ uint32_t smem_u32(const void* p) {
    uint32_t a;
    asm("{ .reg .u64 t; cvta.to.shared.u64 t, %1; cvt.u32.u64 %0, t; }" : "=r"(a) : "l"(p));
    return a;
}
__device__ __forceinline__ uint32_t pack2(float lo, float hi) {
    uint32_t r;
    asm("cvt.rn.f16x2.f32 %0, %1, %2;" : "=r"(r) : "f"(hi), "f"(lo));
    return r;
}
__device__ __forceinline__ void ldsm4(uint32_t* r, uint32_t a) {
    asm volatile("ldmatrix.sync.aligned.m8n8.x4.shared.b16 {%0,%1,%2,%3}, [%4];"
                 : "=r"(r[0]), "=r"(r[1]), "=r"(r[2]), "=r"(r[3]) : "r"(a));
}
__device__ __forceinline__ void ldsm4t(uint32_t* r, uint32_t a) {
    asm volatile("ldmatrix.sync.aligned.m8n8.x4.trans.shared.b16 {%0,%1,%2,%3}, [%4];"
                 : "=r"(r[0]), "=r"(r[1]), "=r"(r[2]), "=r"(r[3]) : "r"(a));
}
__device__ __forceinline__ void mma16(float* c, const uint32_t* a, const uint32_t* b) {
    asm volatile(
        "mma.sync.aligned.m16n8k16.row.col.f32.f16.f16.f32 "
        "{%0,%1,%2,%3},{%4,%5,%6,%7},{%8,%9},{%0,%1,%2,%3};"
        : "+f"(c[0]), "+f"(c[1]), "+f"(c[2]), "+f"(c[3])
        : "r"(a[0]), "r"(a[1]), "r"(a[2]), "r"(a[3]), "r"(b[0]), "r"(b[1]));
}
#define CPA16(dst, src) \
    asm volatile("cp.async.cg.shared.global [%0], [%1], 16;" :: "r"(dst), "l"(src))
#define CPCOMMIT() asm volatile("cp.async.commit_group;" ::: "memory")
#define CPWAIT1()  asm volatile("cp.async.wait_group 1;" ::: "memory")
#define STS128(a, v0, v1, v2, v3) \
    asm volatile("st.shared.v4.b32 [%0], {%1,%2,%3,%4};" :: "r"(a), "r"(v0), "r"(v1), "r"(v2), "r"(v3))

__device__ __forceinline__ float gelu_tanh(float x) {
    float x3 = x * x * x;
    return 0.5f * x * (1.0f + tanhf(0.7978845608028654f * (x + 0.044715f * x3)));
}

// ---------------- router (+ fused hs fp32->fp16 convert + out zeroing) ----------------
__global__ void k_router(const float* __restrict__ hs, const float* __restrict__ gw,
                         float4* __restrict__ out4) {
    // zero the output (poisoned by harness); 256 blocks x 256 threads x 16 float4 = 16 MB
    {
        const int gtid = blockIdx.x * 256 + threadIdx.x;
        const float4 z = make_float4(0.f, 0.f, 0.f, 0.f);
#pragma unroll
        for (int j = 0; j < 16; j++) out4[gtid + j * 65536] = z;
    }
    const int warp = threadIdx.x >> 5;
    const int lane = threadIdx.x & 31;
    const int t = blockIdx.x * 8 + warp;
    if (t >= TTOK) return;
    float acc[NEXP];
#pragma unroll
    for (int e = 0; e < NEXP; e++) acc[e] = 0.0f;
    const float2* hrow2 = (const float2*)(hs + (size_t)t * DDIM);
    uint32_t* xrow = (uint32_t*)(g_x16 + (size_t)t * DDIM);
    for (int i = lane; i < DDIM / 2; i += 32) {
        float2 x = hrow2[i];
        xrow[i] = pack2(x.x, x.y);
        const float* g0 = gw + (size_t)(2 * i) * NEXP;
#pragma unroll
        for (int e = 0; e < NEXP; e++)
            acc[e] = fmaf(x.x, g0[e], fmaf(x.y, g0[NEXP + e], acc[e]));
    }
#pragma unroll
    for (int e = 0; e < NEXP; e++) {
#pragma unroll
        for (int o = 16; o > 0; o >>= 1) acc[e] += __shfl_xor_sync(0xffffffffu, acc[e], o);
    }
    if (lane == 0) {
        float l[NEXP];
#pragma unroll
        for (int e = 0; e < NEXP; e++) l[e] = tanhf(acc[e] / 30.0f) * 30.0f;
        int i0 = 0;
#pragma unroll
        for (int e = 1; e < NEXP; e++) if (l[e] > l[i0]) i0 = e;
        int i1 = -1;
#pragma unroll
        for (int e = 0; e < NEXP; e++) {
            if (e == i0) continue;
            if (i1 < 0 || l[e] > l[i1]) i1 = e;
        }
        float ee = expf(l[i1] - l[i0]);
        g_topk_idx[t * 2 + 0] = i0;
        g_topk_idx[t * 2 + 1] = i1;
        g_topk_w[t * 2 + 0] = 1.0f / (1.0f + ee);
        g_topk_w[t * 2 + 1] = ee / (1.0f + ee);
    }
}

// ---------------- prep: counts + offsets + fill + compact tile map (one block) --------
__global__ void k_prep() {
    __shared__ int cnt[NEXP];
    __shared__ int fill[NEXP];
    const int tid = threadIdx.x;
    if (tid < NEXP) cnt[tid] = 0;
    __syncthreads();
    for (int i = tid; i < NPOS; i += blockDim.x) atomicAdd(&cnt[g_topk_idx[i]], 1);
    __syncthreads();
    if (tid == 0) {
        int o = 0;
        int nt = 0;
#pragma unroll
        for (int e = 0; e < NEXP; e++) {
            g_offsets[e] = o;
            fill[e] = o;
            const int seg = cnt[e];
            for (int b = 0; b < seg; b += 128) {
                g_tile_e[nt] = e;
                g_tile_base[nt] = o + b;
                nt++;
            }
            o += seg;
        }
        g_offsets[NEXP] = o;
        g_tile_cnt = nt;
    }
    __syncthreads();
    for (int i = tid; i < NPOS; i += blockDim.x) {
        const int e = g_topk_idx[i];
        const int pos = atomicAdd(&fill[e], 1);
        g_row_token[pos] = i >> 1;
        g_row_w[pos] = g_topk_w[i];
    }
}

// ============ mlp1: act = gelu(X@Wg) * (X@Wu) ============
// 256 threads = 8 warps (2m x 4n), CTA tile 128x128 (64 gate + 64 up interleaved by 8 cols),
// K-chunk 32; A via cp.async, B via LDG fp32 + cvt + STS (conflict-free 128B-split stores).
// Grid x = compact tile index (expert + m-base via lookup), y = f-tile.
__global__ void __launch_bounds__(256, 2) k_mlp1(const float* __restrict__ wgf,
                                                 const float* __restrict__ wuf) {
    extern __shared__ uint8_t dsm[];
    if ((int)blockIdx.x >= g_tile_cnt) return;
    const int e = g_tile_e[blockIdx.x];
    const int pos_base = g_tile_base[blockIdx.x];
    const int seg_end = g_offsets[e + 1];
    const int f0 = blockIdx.y * 64;

    const uint32_t sbase = smem_u32(dsm);
    const int tid = threadIdx.x;
    const int lane = tid & 31;
    const int w = tid >> 5, wm = w & 1, wn = w >> 1;
    const int grp = lane >> 3;

    // A producer: row tid>>1 (0..127), half tid&1; per-row gathered token pointer
    int apos = pos_base + (tid >> 1);
    if (apos >= seg_end) apos = seg_end - 1;
    const __half* asrc = g_x16 + (size_t)g_row_token[apos] * DDIM + (tid & 1) * 16;
    const uint32_t adst = (uint32_t)(tid >> 1) * ASTR + (uint32_t)(tid & 1) * 32;

    // B producer: h = gate/up, krow = u>>2 (0..31), c = u&3.
    // Thread covers f-cols [8c,8c+8) and [8c+32,8c+40) of matrix h; stores 128B apart.
    const int h = tid >> 7;
    const int u = tid & 127;
    const int krow = u >> 2;
    const int c = u & 3;
    const float* bsrc0 = (h ? wuf : wgf) + (size_t)e * DDIM * FDIM + (size_t)krow * FDIM + f0 + c * 8;
    const uint32_t bdst0 = A_SZ + (uint32_t)krow * BSTR + (uint32_t)c * 32 + (uint32_t)h * 16;

    float acc[4][4][4];
#pragma unroll
    for (int a = 0; a < 4; a++)
#pragma unroll
        for (int b = 0; b < 4; b++)
#pragma unroll
            for (int i = 0; i < 4; i++) acc[a][b][i] = 0.0f;

    const int KT = DDIM / 32;  // 64
    float4 rb[4];

    // prologue: fill stages 0,1; preload regs for chunk 2
#pragma unroll 1
    for (int s = 0; s < 2; s++) {
        const uint32_t st = sbase + s * STAGE;
        const size_t k0 = (size_t)s * 32;
        rb[0] = *(const float4*)(bsrc0 + k0 * FDIM);
        rb[1] = *(const float4*)(bsrc0 + k0 * FDIM + 4);
        rb[2] = *(const float4*)(bsrc0 + k0 * FDIM + 32);
        rb[3] = *(const float4*)(bsrc0 + k0 * FDIM + 36);
        STS128(st + bdst0, pack2(rb[0].x, rb[0].y), pack2(rb[0].z, rb[0].w),
                           pack2(rb[1].x, rb[1].y), pack2(rb[1].z, rb[1].w));
        STS128(st + bdst0 + 128, pack2(rb[2].x, rb[2].y), pack2(rb[2].z, rb[2].w),
                                 pack2(rb[3].x, rb[3].y), pack2(rb[3].z, rb[3].w));
        CPA16(st + adst, asrc + k0);
        CPA16(st + adst + 16, asrc + k0 + 8);
        CPCOMMIT();
    }
    rb[0] = *(const float4*)(bsrc0 + (size_t)64 * FDIM);
    rb[1] = *(const float4*)(bsrc0 + (size_t)64 * FDIM + 4);
    rb[2] = *(const float4*)(bsrc0 + (size_t)64 * FDIM + 32);
    rb[3] = *(const float4*)(bsrc0 + (size_t)64 * FDIM + 36);

#pragma unroll 1
    for (int c2 = 0; c2 < KT; c2++) {
        CPWAIT1();
        __syncthreads();
        if (c2 + 2 < KT) {
            const uint32_t st = sbase + ((c2 + 2) % NSTG) * STAGE;
            const size_t k0 = (size_t)(c2 + 2) * 32;
            STS128(st + bdst0, pack2(rb[0].x, rb[0].y), pack2(rb[0].z, rb[0].w),
                               pack2(rb[1].x, rb[1].y), pack2(rb[1].z, rb[1].w));
            STS128(st + bdst0 + 128, pack2(rb[2].x, rb[2].y), pack2(rb[2].z, rb[2].w),
                                     pack2(rb[3].x, rb[3].y), pack2(rb[3].z, rb[3].w));
            CPA16(st + adst, asrc + k0);
            CPA16(st + adst + 16, asrc + k0 + 8);
        }
        CPCOMMIT();
        if (c2 + 3 < KT) {
            const size_t k0 = (size_t)(c2 + 3) * 32;
            rb[0] = *(const float4*)(bsrc0 + k0 * FDIM);
            rb[1] = *(const float4*)(bsrc0 + k0 * FDIM + 4);
            rb[2] = *(const float4*)(bsrc0 + k0 * FDIM + 32);
            rb[3] = *(const float4*)(bsrc0 + k0 * FDIM + 36);
        }
        // compute chunk c2
        const uint32_t sA = sbase + (c2 % NSTG) * STAGE;
        const uint32_t sB = sA + A_SZ;
#pragma unroll
        for (int ks = 0; ks < 2; ks++) {
            uint32_t bfr[4][2];
#pragma unroll
            for (int hn = 0; hn < 2; hn++) {
                uint32_t r[4];
                ldsm4t(r, sB + (uint32_t)(ks * 16 + (grp & 1) * 8 + (lane & 7)) * BSTR +
                           (uint32_t)(wn * 32 + hn * 16 + (grp >> 1) * 8) * 2);
                bfr[hn * 2 + 0][0] = r[0]; bfr[hn * 2 + 0][1] = r[1];
                bfr[hn * 2 + 1][0] = r[2]; bfr[hn * 2 + 1][1] = r[3];
            }
#pragma unroll
            for (int mt = 0; mt < 4; mt++) {
                uint32_t afr[4];
                ldsm4(afr, sA + (uint32_t)(wm * 64 + mt * 16 + (grp & 1) * 8 + (lane & 7)) * ASTR +
                           (uint32_t)(ks * 16 + (grp >> 1) * 8) * 2);
#pragma unroll
                for (int nt = 0; nt < 4; nt++) mma16(acc[mt][nt], afr, bfr[nt]);
            }
        }
    }

    // epilogue: nt even = gate, nt odd = up (same 8 f-cols)
#pragma unroll
    for (int mt = 0; mt < 4; mt++) {
        const int r0 = pos_base + wm * 64 + mt * 16 + (lane >> 2);
#pragma unroll
        for (int hn = 0; hn < 2; hn++) {
            const int fc = f0 + (wn * 2 + hn) * 8 + 2 * (lane & 3);
            const float* g = acc[mt][2 * hn];
            const float* uq = acc[mt][2 * hn + 1];
            if (r0 < seg_end)
                *(uint32_t*)(&g_act[(size_t)r0 * FDIM + fc]) =
                    pack2(gelu_tanh(g[0]) * uq[0], gelu_tanh(g[1]) * uq[1]);
            if (r0 + 8 < seg_end)
                *(uint32_t*)(&g_act[(size_t)(r0 + 8) * FDIM + fc]) =
                    pack2(gelu_tanh(g[2]) * uq[2], gelu_tanh(g[3]) * uq[3]);
        }
    }
}

// ============ mlp2: out[token] += w * (act @ Wd)  (fused combine via atomicAdd) ============
__global__ void __launch_bounds__(256, 2) k_mlp2(const float* __restrict__ wdf,
                                                 float* __restrict__ out) {
    extern __shared__ uint8_t dsm[];
    if ((int)blockIdx.x >= g_tile_cnt) return;
    const int e = g_tile_e[blockIdx.x];
    const int pos_base = g_tile_base[blockIdx.x];
    const int seg_end = g_offsets[e + 1];
    const int n0 = blockIdx.y * 128;

    const uint32_t sbase = smem_u32(dsm);
    const int tid = threadIdx.x;
    const int lane = tid & 31;
    const int w = tid >> 5, wm = w & 1, wn = w >> 1;
    const int grp = lane >> 3;

    int apos = pos_base + (tid >> 1);
    if (apos >= seg_end) apos = seg_end - 1;
    const __half* asrc = g_act + (size_t)apos * FDIM + (tid & 1) * 16;
    const uint32_t adst = (uint32_t)(tid >> 1) * ASTR + (uint32_t)(tid & 1) * 32;

    const int krow = tid >> 3;           // 0..31
    const int c8 = tid & 7;              // 8-col group
    const float* bsrc0 = wdf + (size_t)e * FDIM * DDIM + (size_t)krow * DDIM + n0 + c8 * 8;
    const uint32_t bdst0 = A_SZ + (uint32_t)krow * BSTR + (uint32_t)c8 * 16;

    float acc[4][4][4];
#pragma unroll
    for (int a = 0; a < 4; a++)
#pragma unroll
        for (int b = 0; b < 4; b++)
#pragma unroll
            for (int i = 0; i < 4; i++) acc[a][b][i] = 0.0f;

    const int KT = FDIM / 32;  // 128
    float4 rb[4];

#pragma unroll 1
    for (int s = 0; s < 2; s++) {
        const uint32_t st = sbase + s * STAGE;
        const size_t k0 = (size_t)s * 32;
        rb[0] = *(const float4*)(bsrc0 + k0 * DDIM);
        rb[1] = *(const float4*)(bsrc0 + k0 * DDIM + 4);
        rb[2] = *(const float4*)(bsrc0 + k0 * DDIM + 64);
        rb[3] = *(const float4*)(bsrc0 + k0 * DDIM + 68);
        STS128(st + bdst0, pack2(rb[0].x, rb[0].y), pack2(rb[0].z, rb[0].w),
                           pack2(rb[1].x, rb[1].y), pack2(rb[1].z, rb[1].w));
        STS128(st + bdst0 + 128, pack2(rb[2].x, rb[2].y), pack2(rb[2].z, rb[2].w),
                                 pack2(rb[3].x, rb[3].y), pack2(rb[3].z, rb[3].w));
        CPA16(st + adst, asrc + k0);
        CPA16(st + adst + 16, asrc + k0 + 8);
        CPCOMMIT();
    }
    rb[0] = *(const float4*)(bsrc0 + (size_t)64 * DDIM);
    rb[1] = *(const float4*)(bsrc0 + (size_t)64 * DDIM + 4);
    rb[2] = *(const float4*)(bsrc0 + (size_t)64 * DDIM + 64);
    rb[3] = *(const float4*)(bsrc0 + (size_t)64 * DDIM + 68);

#pragma unroll 1
    for (int c = 0; c < KT; c++) {
        CPWAIT1();
        __syncthreads();
        if (c + 2 < KT) {
            const uint32_t st = sbase + ((c + 2) % NSTG) * STAGE;
            const size_t k0 = (size_t)(c + 2) * 32;
            STS128(st + bdst0, pack2(rb[0].x, rb[0].y), pack2(rb[0].z, rb[0].w),
                               pack2(rb[1].x, rb[1].y), pack2(rb[1].z, rb[1].w));
            STS128(st + bdst0 + 128, pack2(rb[2].x, rb[2].y), pack2(rb[2].z, rb[2].w),
                                     pack2(rb[3].x, rb[3].y), pack2(rb[3].z, rb[3].w));
            CPA16(st + adst, asrc + k0);
            CPA16(st + adst + 16, asrc + k0 + 8);
        }
        CPCOMMIT();
        if (c + 3 < KT) {
            const size_t k0 = (size_t)(c + 3) * 32;
            rb[0] = *(const float4*)(bsrc0 + k0 * DDIM);
            rb[1] = *(const float4*)(bsrc0 + k0 * DDIM + 4);
            rb[2] = *(const float4*)(bsrc0 + k0 * DDIM + 64);
            rb[3] = *(const float4*)(bsrc0 + k0 * DDIM + 68);
        }
        const uint32_t sA = sbase + (c % NSTG) * STAGE;
        const uint32_t sB = sA + A_SZ;
#pragma unroll
        for (int ks = 0; ks < 2; ks++) {
            uint32_t bfr[4][2];
#pragma unroll
            for (int hn = 0; hn < 2; hn++) {
                uint32_t r[4];
                ldsm4t(r, sB + (uint32_t)(ks * 16 + (grp & 1) * 8 + (lane & 7)) * BSTR +
                           (uint32_t)(wn * 32 + hn * 16 + (grp >> 1) * 8) * 2);
                bfr[hn * 2 + 0][0] = r[0]; bfr[hn * 2 + 0][1] = r[1];
                bfr[hn * 2 + 1][0] = r[2]; bfr[hn * 2 + 1][1] = r[3];
            }
#pragma unroll
            for (int mt = 0; mt < 4; mt++) {
                uint32_t afr[4];
                ldsm4(afr, sA + (uint32_t)(wm * 64 + mt * 16 + (grp & 1) * 8 + (lane & 7)) * ASTR +
                           (uint32_t)(ks * 16 + (grp >> 1) * 8) * 2);
#pragma unroll
                for (int nt = 0; nt < 4; nt++) mma16(acc[mt][nt], afr, bfr[nt]);
            }
        }
    }

    // epilogue: out[token] += w * acc (fused combine; spread-address scatter-add)
#pragma unroll
    for (int mt = 0; mt < 4; mt++) {
        const int r0 = pos_base + wm * 64 + mt * 16 + (lane >> 2);
        const int r1 = r0 + 8;
        const bool v0 = r0 < seg_end, v1 = r1 < seg_end;
        const float w0 = v0 ? g_row_w[r0] : 0.0f;
        const float w1 = v1 ? g_row_w[r1] : 0.0f;
        float* o0 = v0 ? out + (size_t)g_row_token[r0] * DDIM : out;
        float* o1 = v1 ? out + (size_t)g_row_token[r1] * DDIM : out;
#pragma unroll
        for (int nt = 0; nt < 4; nt++) {
            const int n = n0 + wn * 32 + nt * 8 + 2 * (lane & 3);
            if (v0) {
                atomicAdd(o0 + n, w0 * acc[mt][nt][0]);
                atomicAdd(o0 + n + 1, w0 * acc[mt][nt][1]);
            }
            if (v1) {
                atomicAdd(o1 + n, w1 * acc[mt][nt][2]);
                atomicAdd(o1 + n + 1, w1 * acc[mt][nt][3]);
            }
        }
    }
}

// ---------------- launch ----------------
extern "C" void kernel_launch(void* const* d_in, const int* in_sizes, int n_in,
                              void* d_out, int out_size) {
    (void)in_sizes; (void)n_in; (void)out_size;
    const float* hs = (const float*)d_in[0];
    const float* gw = (const float*)d_in[1];
    const float* wg = (const float*)d_in[2];
    const float* wu = (const float*)d_in[3];
    const float* wd = (const float*)d_in[4];
    float* out = (float*)d_out;

    cudaFuncSetAttribute(k_mlp1, cudaFuncAttributeMaxDynamicSharedMemorySize, DYNSM);
    cudaFuncSetAttribute(k_mlp2, cudaFuncAttributeMaxDynamicSharedMemorySize, DYNSM);

    k_router<<<TTOK / 8, 256>>>(hs, gw, (float4*)out);                  // #1 (+cvt hs, +zero out)
    k_prep<<<1, 1024>>>();                                              // #2 (scan+assign+tile map)
    k_mlp1<<<dim3(MAXTILE, FDIM / 64, 1), 256, DYNSM>>>(wg, wu);        // #3
    k_mlp2<<<dim3(MAXTILE, DDIM / 128, 1), 256, DYNSM>>>(wd, out);      // #4 (fused combine)
}